// round 12
// baseline (speedup 1.0000x reference)
#include <cuda_runtime.h>
#include <math.h>

#define NB 8
#define NH 12
#define NS 8192
#define ND 64
#define NBH (NB * NH)
#define KSEL 1024
#define NT2 1024
#define PER4 (NS / NT2 / 2)   // 4 iters x 2 elems

#define NSM 152
#define SRT 256           // score threads per CTA
#define TROWS 256         // rows per score tile
#define NTILES (NBH * NS / TROWS)        // 3072
#define TPB (NS / TROWS)                 // 32 tiles per bh
#define SK_F4 (TROWS * 17)
#define DYN_SMEM ((2 * SK_F4 + 32) * 16)

// device scratch (no allocs allowed)
__device__ float2 g_sg[NBH * NS];        // (score, gumbel) interleaved
__device__ unsigned g_maxpart[NTILES];   // per-tile encoded max

// ---------------- Threefry-2x32 (JAX), key = (0, 42) ----------------
__device__ __forceinline__ unsigned rotl32(unsigned x, int r) {
    return __funnelshift_l(x, x, r);
}

__device__ __forceinline__ void threefry2x32_0_42(unsigned c0, unsigned c1,
                                                  unsigned& o0, unsigned& o1) {
    const unsigned ks0 = 0u;
    const unsigned ks1 = 42u;
    const unsigned ks2 = 0x1BD11BDAu ^ 0u ^ 42u;
    unsigned x0 = c0 + ks0;
    unsigned x1 = c1 + ks1;
#define TF_R(r) { x0 += x1; x1 = rotl32(x1, (r)); x1 ^= x0; }
    TF_R(13) TF_R(15) TF_R(26) TF_R(6)
    x0 += ks1; x1 += ks2 + 1u;
    TF_R(17) TF_R(29) TF_R(16) TF_R(24)
    x0 += ks2; x1 += ks0 + 2u;
    TF_R(13) TF_R(15) TF_R(26) TF_R(6)
    x0 += ks0; x1 += ks1 + 3u;
    TF_R(17) TF_R(29) TF_R(16) TF_R(24)
    x0 += ks1; x1 += ks2 + 4u;
    TF_R(13) TF_R(15) TF_R(26) TF_R(6)
    x0 += ks2; x1 += ks0 + 5u;
#undef TF_R
    o0 = x0; o1 = x1;
}

// ---------------- accurate fp32 exp/log (fast-math immune, ~1 ulp) ----------------
__device__ __forceinline__ float f_exp(float x) {
    float n = rintf(x * 1.4426950408889634f);
    float r = __fmaf_rn(n, -0.693359375f, x);
    r = __fmaf_rn(n, 2.12194440e-4f, r);
    float p = 1.9841270e-4f;
    p = __fmaf_rn(p, r, 1.3888889e-3f);
    p = __fmaf_rn(p, r, 8.3333333e-3f);
    p = __fmaf_rn(p, r, 4.1666668e-2f);
    p = __fmaf_rn(p, r, 1.6666667e-1f);
    p = __fmaf_rn(p, r, 0.5f);
    float e = __fmaf_rn(p, r * r, r) + 1.0f;
    int ni = (int)n;
    ni = max(-126, min(127, ni));
    e *= __uint_as_float((unsigned)(ni + 127) << 23);
    return e;
}

__device__ __forceinline__ float f_log(float x) {
    unsigned u = __float_as_uint(x);
    int e = (int)(u >> 23) - 127;
    float m = __uint_as_float((u & 0x007fffffu) | 0x3f800000u);
    if (m > 1.4142135f) { m = m * 0.5f; e += 1; }
    float fe = (float)e;
    float s = __fdiv_rn(m - 1.0f, m + 1.0f);
    float s2 = s * s;
    float p = 0.11111111f;
    p = __fmaf_rn(p, s2, 0.14285715f);
    p = __fmaf_rn(p, s2, 0.2f);
    p = __fmaf_rn(p, s2, 0.33333334f);
    float w = s + s;
    float lm = __fmaf_rn(w * s2, p, w);
    float r = __fmaf_rn(fe, -2.12194440e-4f, lm);
    r = __fmaf_rn(fe, 0.693359375f, r);
    return r;
}

// ---------------- JAX gumbel(key=42) at flat index i ----------------
__device__ __forceinline__ float gumbel_at(unsigned i) {
    unsigned o0, o1;
    threefry2x32_0_42(0u, i, o0, o1);
    unsigned bits = o0 ^ o1;
    float f = __uint_as_float((bits >> 9) | 0x3f800000u) - 1.0f;   // [0,1)
    const float tiny = 1.17549435e-38f;
    float uu = f * (1.0f - tiny) + tiny;
    uu = fmaxf(tiny, uu);
    return -f_log(-f_log(uu));
}

// monotone float -> sortable uint (and inverse)
__device__ __forceinline__ unsigned f2k(float v) {
    unsigned u = __float_as_uint(v);
    return (u & 0x80000000u) ? ~u : (u | 0x80000000u);
}
__device__ __forceinline__ float k2f(unsigned k) {
    return (k & 0x80000000u) ? __uint_as_float(k & 0x7fffffffu)
                             : __uint_as_float(~k);
}

__device__ __forceinline__ void cp16(float4* dst_smem, const float4* src) {
    unsigned d = (unsigned)__cvta_generic_to_shared(dst_smem);
    asm volatile("cp.async.cg.shared.global [%0], [%1], 16;" :: "r"(d), "l"(src));
}

// ---------------- kernel 1: persistent streaming scores + gumbel + per-tile max (R8) ----------------
__global__ void __launch_bounds__(SRT) score_kernel(const float* __restrict__ q,
                                                    const float* __restrict__ k) {
    extern __shared__ float4 dsm[];
    float4* skbuf = dsm;                 // [2][SK_F4]
    float4* qb = dsm + 2 * SK_F4;        // [2][16]
    __shared__ unsigned redmax[8];

    int c = blockIdx.x;
    int t = threadIdx.x;
    // contiguous tile runs: 3072 = 152*20 + 32 -> CTAs 0..31 get 21 tiles
    int start = (c < 32) ? c * 21 : 20 * c + 32;
    int len = (c < 32) ? 21 : 20;

    const float4* k4 = (const float4*)k;

#pragma unroll
    for (int pn = 0; pn < 2; ++pn) {
        int tile = start + pn;
        float4* buf = skbuf + pn * SK_F4;
        if (t < 16) {
            int bh = tile / TPB;
            qb[pn * 16 + t] = ((const float4*)(q + (size_t)bh * NS * ND))[t];
        }
        const float4* kg = k4 + (size_t)tile * (TROWS * 16);
#pragma unroll
        for (int i = 0; i < 16; ++i) {
            int L = i * SRT + t;
            cp16(&buf[(L >> 4) * 17 + (L & 15)], kg + L);
        }
        asm volatile("cp.async.commit_group;" ::: "memory");
    }

    for (int n = 0; n < len; ++n) {
        int tile = start + n;
        int slot = n & 1;
        float4* buf = skbuf + slot * SK_F4;

        if (n + 1 < len) {
            asm volatile("cp.async.wait_group 1;" ::: "memory");
        } else {
            asm volatile("cp.async.wait_group 0;" ::: "memory");
        }
        __syncthreads();

        float4 acc = make_float4(0.f, 0.f, 0.f, 0.f);
#pragma unroll
        for (int j = 0; j < 16; ++j) {
            float4 kv = buf[t * 17 + j];
            float4 qv = qb[slot * 16 + j];
            acc.x = __fmaf_rn(qv.x, kv.x, acc.x);
            acc.y = __fmaf_rn(qv.y, kv.y, acc.y);
            acc.z = __fmaf_rn(qv.z, kv.z, acc.z);
            acc.w = __fmaf_rn(qv.w, kv.w, acc.w);
        }
        float dot = ((acc.x + acc.y) + (acc.z + acc.w)) * 0.125f;
        unsigned flat = (unsigned)tile * TROWS + t;     // == bh*NS + s
        g_sg[flat] = make_float2(dot, gumbel_at(flat));

        float cmax = dot;
        for (int o = 16; o; o >>= 1) cmax = fmaxf(cmax, __shfl_xor_sync(0xffffffffu, cmax, o));
        if ((t & 31) == 0) redmax[t >> 5] = f2k(cmax);
        __syncthreads();   // redmax ready AND all buf/qb reads complete
        if (t == 0) {
            unsigned m = redmax[0];
#pragma unroll
            for (int i = 1; i < 8; ++i) m = max(m, redmax[i]);
            g_maxpart[tile] = m;
        }

        if (n + 2 < len) {
            int tile2 = start + n + 2;
            if (t < 16) {
                int bh2 = tile2 / TPB;
                qb[slot * 16 + t] = ((const float4*)(q + (size_t)bh2 * NS * ND))[t];
            }
            const float4* kg2 = k4 + (size_t)tile2 * (TROWS * 16);
#pragma unroll
            for (int i = 0; i < 16; ++i) {
                int L = i * SRT + t;
                cp16(&buf[(L >> 4) * 17 + (L & 15)], kg2 + L);
            }
            asm volatile("cp.async.commit_group;" ::: "memory");
        }
    }
}

// ---------------- kernel 2: softmax + gumbel + radix top-k + scatter ----------------
__global__ void __launch_bounds__(NT2) select_kernel(const float* __restrict__ token_mask,
                                                     float* __restrict__ out) {
    int bh = blockIdx.x;
    int b = bh / NH;
    int tid = threadIdx.x;
    int lane = tid & 31, wid = tid >> 5;
    int hg = wid >> 3;                   // histogram copy 0..3

    __shared__ float shv_f[NS];          // 32 KB, sortable keys
    __shared__ unsigned hist4[4][256];   // replicated histograms
    __shared__ double red_d[32];
    __shared__ unsigned sh_maxe;
    __shared__ float sh_denom;
    __shared__ int sh_bin;
    __shared__ unsigned sh_cum, sh_eq;
    unsigned* shv_u = (unsigned*)shv_f;

    const float4* sg4 = (const float4*)(g_sg + bh * NS);   // 2 elems per float4
    const float2* mk2 = (const float2*)(token_mask + b * NS);

    // front-load all element data (vectorized; LDGs in flight during max gather)
    float4 v[PER4];      // (s0,g0,s1,g1)
    float2 msk[PER4];
#pragma unroll
    for (int it = 0; it < PER4; ++it) {
        int e2 = tid + it * NT2;         // pair index: elements 2*e2, 2*e2+1
        v[it] = sg4[e2];
        msk[it] = mk2[e2];
    }

    // exact row max from 32 per-tile slots (warp 0)
    if (wid == 0) {
        unsigned me = g_maxpart[bh * TPB + lane];
        for (int o = 16; o; o >>= 1) me = max(me, __shfl_xor_sync(0xffffffffu, me, o));
        if (lane == 0) sh_maxe = me;
    }
    __syncthreads();
    float mx = k2f(sh_maxe);

    // pass B: e = exp(score - max) * mask; double sum (rounded once -> order-safe)
    float le[PER4][2];
    double lsum = 0.0;
#pragma unroll
    for (int it = 0; it < PER4; ++it) {
        float e0 = f_exp(v[it].x - mx) * msk[it].x;
        float e1 = f_exp(v[it].z - mx) * msk[it].y;
        le[it][0] = e0; le[it][1] = e1;
        lsum += (double)e0;
        lsum += (double)e1;
    }
    for (int o = 16; o; o >>= 1) lsum += __shfl_xor_sync(0xffffffffu, lsum, o);
    if (lane == 0) red_d[wid] = lsum;
    __syncthreads();
    if (wid == 0) {
        double tt = red_d[lane];
        for (int o = 16; o; o >>= 1) tt += __shfl_xor_sync(0xffffffffu, tt, o);
        if (lane == 0) sh_denom = (float)tt + 1e-6f;
    }
    __syncthreads();
    float denom = sh_denom;

    // pass C: value = log((e + eps/S)/denom) + gumbel ; sortable keys (paired stores)
    const float C1 = (float)(1e-6 / 8192.0);
    unsigned lk[PER4][2];
    uint2* shv_u2 = (uint2*)shv_u;
#pragma unroll
    for (int it = 0; it < PER4; ++it) {
        int e2 = tid + it * NT2;
        float a0 = __fdiv_rn(__fadd_rn(le[it][0], C1), denom);
        float a1 = __fdiv_rn(__fadd_rn(le[it][1], C1), denom);
        unsigned k0 = f2k(__fadd_rn(f_log(a0), v[it].y));
        unsigned k1 = f2k(__fadd_rn(f_log(a1), v[it].w));
        lk[it][0] = k0; lk[it][1] = k1;
        shv_u2[e2] = make_uint2(k0, k1);
    }
    __syncthreads();

    // radix select: threshold key of the KSEL-th largest (ties -> lowest index)
    unsigned prefix = 0, hmask = 0, remain = KSEL, eqTotal = 0;
    for (int byte = 3; byte >= 0; --byte) {
        ((unsigned*)hist4)[tid] = 0;     // 1024 entries cleared by 1024 threads
        __syncthreads();
        int sh = byte * 8;
        // warp-aggregated histogram: lanes sharing a bin elect one leader who
        // adds popc(peers). Exact same counts as per-lane atomics; collapses
        // intra-warp same-address ATOMS serialization on concentrated bins.
#pragma unroll
        for (int it = 0; it < PER4; ++it) {
#pragma unroll
            for (int e = 0; e < 2; ++e) {
                unsigned kk = lk[it][e];
                bool act = ((kk & hmask) == prefix);
                unsigned bin = (kk >> sh) & 0xffu;
                unsigned amask = __ballot_sync(0xffffffffu, act);
                if (act) {
                    unsigned peers = __match_any_sync(amask, bin);
                    int leader = __ffs(peers) - 1;
                    unsigned cnt = (unsigned)__popc(peers);
                    if (lane == leader)
                        atomicAdd(&hist4[hg][bin], cnt);
                }
            }
        }
        __syncthreads();
        // warp-parallel reverse scan over 256 merged bins (warp 0)
        if (wid == 0) {
            unsigned cnt[8];
            unsigned ssum = 0;
#pragma unroll
            for (int qq = 0; qq < 8; ++qq) {
                int bin = lane * 8 + qq;
                cnt[qq] = hist4[0][bin] + hist4[1][bin] + hist4[2][bin] + hist4[3][bin];
                ssum += cnt[qq];
            }
            unsigned x = ssum;
#pragma unroll
            for (int off = 1; off < 32; off <<= 1) {
                unsigned y = __shfl_down_sync(0xffffffffu, x, off);
                if (lane + off < 32) x += y;
            }
            unsigned excl = x - ssum;
            bool hit = (excl < remain) && (x >= remain);
            unsigned hmsk = __ballot_sync(0xffffffffu, hit);
            int hl = __ffs(hmsk) - 1;
            if (lane == hl) {
                unsigned cum = excl;
                int bq = 7;
                for (; bq > 0; --bq) {
                    if (cum + cnt[bq] >= remain) break;
                    cum += cnt[bq];
                }
                sh_bin = lane * 8 + bq;
                sh_cum = cum;
                sh_eq = cnt[bq];
            }
        }
        __syncthreads();
        prefix |= ((unsigned)sh_bin) << sh;
        hmask  |= 0xffu << sh;
        remain -= sh_cum;
        eqTotal = sh_eq;
    }
    __syncthreads();
    unsigned thresh = prefix;
    unsigned need = remain;

    // pass D: boolean output as float (paired stores); p==0 forced true;
    // p>=1 true iff sampled index s=p-1 in top-k (index 8191 -> pos 8192 dropped).
    float2* out2 = (float2*)(out + bh * NS);
#pragma unroll
    for (int it = 0; it < PER4; ++it) {
        int e2 = tid + it * NT2;
        float o01[2];
#pragma unroll
        for (int e = 0; e < 2; ++e) {
            int p = 2 * e2 + e;
            float o;
            if (p == 0) {
                o = 1.0f;
            } else {
                int s = p - 1;
                unsigned kk = shv_u[s];
                if (kk > thresh) {
                    o = 1.0f;
                } else if (kk == thresh) {
                    if (eqTotal == need) {
                        o = 1.0f;
                    } else {
                        unsigned rank = 0;
                        for (int j = 0; j < s; ++j) rank += (shv_u[j] == thresh);
                        o = (rank < need) ? 1.0f : 0.0f;
                    }
                } else {
                    o = 0.0f;
                }
            }
            o01[e] = o;
        }
        out2[e2] = make_float2(o01[0], o01[1]);
    }
}

extern "C" void kernel_launch(void* const* d_in, const int* in_sizes, int n_in,
                              void* d_out, int out_size) {
    const float* q = (const float*)d_in[0];
    const float* k = (const float*)d_in[1];
    // d_in[2] = v : unused by the reference computation
    const float* token_mask = (const float*)d_in[3];

    cudaFuncSetAttribute(score_kernel, cudaFuncAttributeMaxDynamicSharedMemorySize, DYN_SMEM);
    score_kernel<<<NSM, SRT, DYN_SMEM>>>(q, k);
    select_kernel<<<NBH, NT2>>>(token_mask, (float*)d_out);
}

// round 13
// speedup vs baseline: 1.0702x; 1.0702x over previous
#include <cuda_runtime.h>
#include <math.h>

#define NB 8
#define NH 12
#define NS 8192
#define ND 64
#define NBH (NB * NH)
#define KSEL 1024
#define NT2 1024
#define PER4 (NS / NT2 / 2)   // 4 iters x 2 elems

#define NSM 152
#define SRT 256           // score threads per CTA
#define TROWS 256         // rows per score tile
#define NTILES (NBH * NS / TROWS)        // 3072
#define TPB (NS / TROWS)                 // 32 tiles per bh
#define SK_F4 (TROWS * 17)
#define DYN_SMEM ((2 * SK_F4 + 32) * 16)

// select dynamic smem layout (uint words): keys | hist0 | hist1 | gsum
#define SEL_KEYS 0
#define SEL_H0   (NS)
#define SEL_H1   (NS + 2048)
#define SEL_GS   (NS + 4096)
#define SEL_SMEM ((NS + 4096 + 256) * 4)

// device scratch (no allocs allowed)
__device__ float2 g_sg[NBH * NS];        // (score, gumbel) interleaved
__device__ unsigned g_maxpart[NTILES];   // per-tile encoded max

// ---------------- Threefry-2x32 (JAX), key = (0, 42) ----------------
__device__ __forceinline__ unsigned rotl32(unsigned x, int r) {
    return __funnelshift_l(x, x, r);
}

__device__ __forceinline__ void threefry2x32_0_42(unsigned c0, unsigned c1,
                                                  unsigned& o0, unsigned& o1) {
    const unsigned ks0 = 0u;
    const unsigned ks1 = 42u;
    const unsigned ks2 = 0x1BD11BDAu ^ 0u ^ 42u;
    unsigned x0 = c0 + ks0;
    unsigned x1 = c1 + ks1;
#define TF_R(r) { x0 += x1; x1 = rotl32(x1, (r)); x1 ^= x0; }
    TF_R(13) TF_R(15) TF_R(26) TF_R(6)
    x0 += ks1; x1 += ks2 + 1u;
    TF_R(17) TF_R(29) TF_R(16) TF_R(24)
    x0 += ks2; x1 += ks0 + 2u;
    TF_R(13) TF_R(15) TF_R(26) TF_R(6)
    x0 += ks0; x1 += ks1 + 3u;
    TF_R(17) TF_R(29) TF_R(16) TF_R(24)
    x0 += ks1; x1 += ks2 + 4u;
    TF_R(13) TF_R(15) TF_R(26) TF_R(6)
    x0 += ks2; x1 += ks0 + 5u;
#undef TF_R
    o0 = x0; o1 = x1;
}

// ---------------- accurate fp32 exp/log (fast-math immune, ~1 ulp) ----------------
__device__ __forceinline__ float f_exp(float x) {
    float n = rintf(x * 1.4426950408889634f);
    float r = __fmaf_rn(n, -0.693359375f, x);
    r = __fmaf_rn(n, 2.12194440e-4f, r);
    float p = 1.9841270e-4f;
    p = __fmaf_rn(p, r, 1.3888889e-3f);
    p = __fmaf_rn(p, r, 8.3333333e-3f);
    p = __fmaf_rn(p, r, 4.1666668e-2f);
    p = __fmaf_rn(p, r, 1.6666667e-1f);
    p = __fmaf_rn(p, r, 0.5f);
    float e = __fmaf_rn(p, r * r, r) + 1.0f;
    int ni = (int)n;
    ni = max(-126, min(127, ni));
    e *= __uint_as_float((unsigned)(ni + 127) << 23);
    return e;
}

__device__ __forceinline__ float f_log(float x) {
    unsigned u = __float_as_uint(x);
    int e = (int)(u >> 23) - 127;
    float m = __uint_as_float((u & 0x007fffffu) | 0x3f800000u);
    if (m > 1.4142135f) { m = m * 0.5f; e += 1; }
    float fe = (float)e;
    float s = __fdiv_rn(m - 1.0f, m + 1.0f);
    float s2 = s * s;
    float p = 0.11111111f;
    p = __fmaf_rn(p, s2, 0.14285715f);
    p = __fmaf_rn(p, s2, 0.2f);
    p = __fmaf_rn(p, s2, 0.33333334f);
    float w = s + s;
    float lm = __fmaf_rn(w * s2, p, w);
    float r = __fmaf_rn(fe, -2.12194440e-4f, lm);
    r = __fmaf_rn(fe, 0.693359375f, r);
    return r;
}

// ---------------- JAX gumbel(key=42) at flat index i ----------------
__device__ __forceinline__ float gumbel_at(unsigned i) {
    unsigned o0, o1;
    threefry2x32_0_42(0u, i, o0, o1);
    unsigned bits = o0 ^ o1;
    float f = __uint_as_float((bits >> 9) | 0x3f800000u) - 1.0f;   // [0,1)
    const float tiny = 1.17549435e-38f;
    float uu = f * (1.0f - tiny) + tiny;
    uu = fmaxf(tiny, uu);
    return -f_log(-f_log(uu));
}

// monotone float -> sortable uint (and inverse)
__device__ __forceinline__ unsigned f2k(float v) {
    unsigned u = __float_as_uint(v);
    return (u & 0x80000000u) ? ~u : (u | 0x80000000u);
}
__device__ __forceinline__ float k2f(unsigned k) {
    return (k & 0x80000000u) ? __uint_as_float(k & 0x7fffffffu)
                             : __uint_as_float(~k);
}

__device__ __forceinline__ void cp16(float4* dst_smem, const float4* src) {
    unsigned d = (unsigned)__cvta_generic_to_shared(dst_smem);
    asm volatile("cp.async.cg.shared.global [%0], [%1], 16;" :: "r"(d), "l"(src));
}

// ---------------- kernel 1: persistent streaming scores + gumbel + per-tile max (R8) ----------------
__global__ void __launch_bounds__(SRT) score_kernel(const float* __restrict__ q,
                                                    const float* __restrict__ k) {
    extern __shared__ float4 dsm[];
    float4* skbuf = dsm;                 // [2][SK_F4]
    float4* qb = dsm + 2 * SK_F4;        // [2][16]
    __shared__ unsigned redmax[8];

    int c = blockIdx.x;
    int t = threadIdx.x;
    // contiguous tile runs: 3072 = 152*20 + 32 -> CTAs 0..31 get 21 tiles
    int start = (c < 32) ? c * 21 : 20 * c + 32;
    int len = (c < 32) ? 21 : 20;

    const float4* k4 = (const float4*)k;

#pragma unroll
    for (int pn = 0; pn < 2; ++pn) {
        int tile = start + pn;
        float4* buf = skbuf + pn * SK_F4;
        if (t < 16) {
            int bh = tile / TPB;
            qb[pn * 16 + t] = ((const float4*)(q + (size_t)bh * NS * ND))[t];
        }
        const float4* kg = k4 + (size_t)tile * (TROWS * 16);
#pragma unroll
        for (int i = 0; i < 16; ++i) {
            int L = i * SRT + t;
            cp16(&buf[(L >> 4) * 17 + (L & 15)], kg + L);
        }
        asm volatile("cp.async.commit_group;" ::: "memory");
    }

    for (int n = 0; n < len; ++n) {
        int tile = start + n;
        int slot = n & 1;
        float4* buf = skbuf + slot * SK_F4;

        if (n + 1 < len) {
            asm volatile("cp.async.wait_group 1;" ::: "memory");
        } else {
            asm volatile("cp.async.wait_group 0;" ::: "memory");
        }
        __syncthreads();

        float4 acc = make_float4(0.f, 0.f, 0.f, 0.f);
#pragma unroll
        for (int j = 0; j < 16; ++j) {
            float4 kv = buf[t * 17 + j];
            float4 qv = qb[slot * 16 + j];
            acc.x = __fmaf_rn(qv.x, kv.x, acc.x);
            acc.y = __fmaf_rn(qv.y, kv.y, acc.y);
            acc.z = __fmaf_rn(qv.z, kv.z, acc.z);
            acc.w = __fmaf_rn(qv.w, kv.w, acc.w);
        }
        float dot = ((acc.x + acc.y) + (acc.z + acc.w)) * 0.125f;
        unsigned flat = (unsigned)tile * TROWS + t;     // == bh*NS + s
        g_sg[flat] = make_float2(dot, gumbel_at(flat));

        float cmax = dot;
        for (int o = 16; o; o >>= 1) cmax = fmaxf(cmax, __shfl_xor_sync(0xffffffffu, cmax, o));
        if ((t & 31) == 0) redmax[t >> 5] = f2k(cmax);
        __syncthreads();   // redmax ready AND all buf/qb reads complete
        if (t == 0) {
            unsigned m = redmax[0];
#pragma unroll
            for (int i = 1; i < 8; ++i) m = max(m, redmax[i]);
            g_maxpart[tile] = m;
        }

        if (n + 2 < len) {
            int tile2 = start + n + 2;
            if (t < 16) {
                int bh2 = tile2 / TPB;
                qb[slot * 16 + t] = ((const float4*)(q + (size_t)bh2 * NS * ND))[t];
            }
            const float4* kg2 = k4 + (size_t)tile2 * (TROWS * 16);
#pragma unroll
            for (int i = 0; i < 16; ++i) {
                int L = i * SRT + t;
                cp16(&buf[(L >> 4) * 17 + (L & 15)], kg2 + L);
            }
            asm volatile("cp.async.commit_group;" ::: "memory");
        }
    }
}

// ---------------- kernel 2: softmax + gumbel + 3-pass radix top-k + scatter ----------------
__global__ void __launch_bounds__(NT2) select_kernel(const float* __restrict__ token_mask,
                                                     float* __restrict__ out) {
    extern __shared__ unsigned ssm[];
    unsigned* shv_u = ssm + SEL_KEYS;    // [NS] sortable keys
    unsigned* hists[2] = { ssm + SEL_H0, ssm + SEL_H1 };   // [2048] each
    unsigned* gsum = ssm + SEL_GS;       // [256] group sums

    __shared__ double red_d[32];
    __shared__ unsigned sh_maxe;
    __shared__ float sh_denom;
    __shared__ int sh_bin;
    __shared__ unsigned sh_cum, sh_eq;

    int bh = blockIdx.x;
    int b = bh / NH;
    int tid = threadIdx.x;
    int lane = tid & 31, wid = tid >> 5;

    const float4* sg4 = (const float4*)(g_sg + bh * NS);   // 2 elems per float4
    const float2* mk2 = (const float2*)(token_mask + b * NS);

    // front-load all element data (vectorized; LDGs in flight during clears/gather)
    float4 v[PER4];      // (s0,g0,s1,g1)
    float2 msk[PER4];
#pragma unroll
    for (int it = 0; it < PER4; ++it) {
        int e2 = tid + it * NT2;
        v[it] = sg4[e2];
        msk[it] = mk2[e2];
    }

    // clear pass-0 histogram (2048 entries, 2 per thread)
    hists[0][tid] = 0;
    hists[0][tid + 1024] = 0;

    // exact row max from 32 per-tile slots (warp 0, shfl only)
    if (wid == 0) {
        unsigned me = g_maxpart[bh * TPB + lane];
        for (int o = 16; o; o >>= 1) me = max(me, __shfl_xor_sync(0xffffffffu, me, o));
        if (lane == 0) sh_maxe = me;
    }
    __syncthreads();
    float mx = k2f(sh_maxe);

    // pass B: e = exp(score - max) * mask; double sum (rounded once -> order-safe)
    float le[PER4][2];
    double lsum = 0.0;
#pragma unroll
    for (int it = 0; it < PER4; ++it) {
        float e0 = f_exp(v[it].x - mx) * msk[it].x;
        float e1 = f_exp(v[it].z - mx) * msk[it].y;
        le[it][0] = e0; le[it][1] = e1;
        lsum += (double)e0;
        lsum += (double)e1;
    }
    for (int o = 16; o; o >>= 1) lsum += __shfl_xor_sync(0xffffffffu, lsum, o);
    if (lane == 0) red_d[wid] = lsum;
    __syncthreads();
    if (wid == 0) {
        double tt = red_d[lane];
        for (int o = 16; o; o >>= 1) tt += __shfl_xor_sync(0xffffffffu, tt, o);
        if (lane == 0) sh_denom = (float)tt + 1e-6f;
    }
    __syncthreads();
    float denom = sh_denom;

    // pass C: value = log((e + eps/S)/denom) + gumbel ; sortable keys (paired stores)
    const float C1 = (float)(1e-6 / 8192.0);
    unsigned lk[PER4][2];
    uint2* shv_u2 = (uint2*)shv_u;
#pragma unroll
    for (int it = 0; it < PER4; ++it) {
        int e2 = tid + it * NT2;
        float a0 = __fdiv_rn(__fadd_rn(le[it][0], C1), denom);
        float a1 = __fdiv_rn(__fadd_rn(le[it][1], C1), denom);
        unsigned k0 = f2k(__fadd_rn(f_log(a0), v[it].y));
        unsigned k1 = f2k(__fadd_rn(f_log(a1), v[it].w));
        lk[it][0] = k0; lk[it][1] = k1;
        shv_u2[e2] = make_uint2(k0, k1);
    }
    __syncthreads();

    // 3-pass radix select: 11 + 11 + 10 bits; threshold = KSEL-th largest key
    const int SHIFTS[3] = {21, 10, 0};
    const int NBIN[3]   = {2048, 2048, 1024};
    unsigned prefix = 0, hmask = 0, remain = KSEL, eqTotal = 0;

    for (int ps = 0; ps < 3; ++ps) {
        unsigned* hc = hists[ps & 1];          // current (pre-cleared)
        unsigned* hn = hists[(ps + 1) & 1];    // next (clear during scan)
        int sh = SHIFTS[ps];
        unsigned bmask = (unsigned)(NBIN[ps] - 1);
        int G = NBIN[ps] >> 8;                 // bins per stage-1 group

        // build histogram
#pragma unroll
        for (int it = 0; it < PER4; ++it) {
#pragma unroll
            for (int e = 0; e < 2; ++e) {
                unsigned kk = lk[it][e];
                if ((kk & hmask) == prefix)
                    atomicAdd(&hc[(kk >> sh) & bmask], 1u);
            }
        }
        __syncthreads();

        // stage 1: threads 0..255 sum G consecutive bins; warps 8..31 clear next hist
        if (tid < 256) {
            unsigned s = 0;
            for (int i = 0; i < G; ++i) s += hc[tid * G + i];
            gsum[tid] = s;
        } else if (ps < 2) {
            for (int i = tid - 256; i < 2048; i += NT2 - 256) hn[i] = 0;
        }
        __syncthreads();

        // stage 2: warp 0 suffix-scan over 256 groups, then drill down
        if (wid == 0) {
            unsigned wsum = 0;
            int gbase = lane * 8;
#pragma unroll
            for (int gq = 0; gq < 8; ++gq) wsum += gsum[gbase + gq];
            unsigned x = wsum;
#pragma unroll
            for (int off = 1; off < 32; off <<= 1) {
                unsigned y = __shfl_down_sync(0xffffffffu, x, off);
                if (lane + off < 32) x += y;
            }
            unsigned excl = x - wsum;          // keys in groups above this lane's 8
            bool hit = (excl < remain) && (x >= remain);
            unsigned hmsk = __ballot_sync(0xffffffffu, hit);
            int hl = __ffs(hmsk) - 1;
            if (lane == hl) {
                unsigned cum = excl;
                int gq = 7;
                for (; gq > 0; --gq) {
                    unsigned c = gsum[gbase + gq];
                    if (cum + c >= remain) break;
                    cum += c;
                }
                int g = gbase + gq;
                int bq = G - 1;
                for (; bq > 0; --bq) {
                    unsigned c = hc[g * G + bq];
                    if (cum + c >= remain) break;
                    cum += c;
                }
                sh_bin = g * G + bq;
                sh_cum = cum;
                sh_eq = hc[g * G + bq];
            }
        }
        __syncthreads();
        prefix |= ((unsigned)sh_bin) << sh;
        hmask  |= bmask << sh;
        remain -= sh_cum;
        eqTotal = sh_eq;
    }
    __syncthreads();
    unsigned thresh = prefix;
    unsigned need = remain;

    // pass D: boolean output as float (paired stores); p==0 forced true;
    // p>=1 true iff sampled index s=p-1 in top-k (index 8191 -> pos 8192 dropped).
    float2* out2 = (float2*)(out + bh * NS);
#pragma unroll
    for (int it = 0; it < PER4; ++it) {
        int e2 = tid + it * NT2;
        float o01[2];
#pragma unroll
        for (int e = 0; e < 2; ++e) {
            int p = 2 * e2 + e;
            float o;
            if (p == 0) {
                o = 1.0f;
            } else {
                int s = p - 1;
                unsigned kk = shv_u[s];
                if (kk > thresh) {
                    o = 1.0f;
                } else if (kk == thresh) {
                    if (eqTotal == need) {
                        o = 1.0f;
                    } else {
                        unsigned rank = 0;
                        for (int j = 0; j < s; ++j) rank += (shv_u[j] == thresh);
                        o = (rank < need) ? 1.0f : 0.0f;
                    }
                } else {
                    o = 0.0f;
                }
            }
            o01[e] = o;
        }
        out2[e2] = make_float2(o01[0], o01[1]);
    }
}

extern "C" void kernel_launch(void* const* d_in, const int* in_sizes, int n_in,
                              void* d_out, int out_size) {
    const float* q = (const float*)d_in[0];
    const float* k = (const float*)d_in[1];
    // d_in[2] = v : unused by the reference computation
    const float* token_mask = (const float*)d_in[3];

    cudaFuncSetAttribute(score_kernel, cudaFuncAttributeMaxDynamicSharedMemorySize, DYN_SMEM);
    cudaFuncSetAttribute(select_kernel, cudaFuncAttributeMaxDynamicSharedMemorySize, SEL_SMEM);
    score_kernel<<<NSM, SRT, DYN_SMEM>>>(q, k);
    select_kernel<<<NBH, NT2, SEL_SMEM>>>(token_mask, (float*)d_out);
}